// round 14
// baseline (speedup 1.0000x reference)
#include <cuda_runtime.h>
#include <cuda_bf16.h>

using u32 = unsigned int;
using u64 = unsigned long long;

// Problem constants (fixed by setup_inputs)
constexpr int B = 4, S = 4096, D = 256, M = 256, H = 8;
constexpr int SK = 16;                  // split-K chunks for ctx GEMM
constexpr float LNEPS = 1e-5f;
constexpr float KEPS  = 1e-4f;
constexpr float DN    = 0.25f;          // 256^-0.25
constexpr float RATIO = 0.0625f;        // 256^-0.5
constexpr float RKEPS = RATIO * KEPS;

// ---------------- device scratch (no allocation APIs allowed) --------------
__device__ float g_diag[B * S];
__device__ __nv_bfloat16 g_ah[B * S * D], g_al[B * S * D];   // split(DN*xn) [s,d]
__device__ __nv_bfloat16 g_pbh[M * D],   g_pbl[M * D];       // split(proj)  [m,d]
__device__ float g_pd[B * S * M];                 // projection, fp32
__device__ float g_rowmax[B * S];                 // atomicMax targets
__device__ float g_bmax[B];
__device__ float g_pksum[B * SK * M];
__device__ float g_ksum[B * M];
__device__ float g_pctx[B * SK * M * D];          // split-K ctx partials (DN-scaled)
__device__ __nv_bfloat16 g_cth[B * M * D], g_ctl[B * M * D]; // split(ctx) [m,d]

// ---------------- PTX helpers (plain sm_103-safe: mma.sync/ldmatrix/cp.async)
__device__ __forceinline__ u32 s2u(const void* p) {
    u32 a;
    asm("{ .reg .u64 t; cvta.to.shared.u64 t, %1; cvt.u32.u64 %0, t; }"
        : "=r"(a) : "l"(p));
    return a;
}
#define LDM4(r, a) \
    asm volatile("ldmatrix.sync.aligned.m8n8.x4.shared.b16 {%0,%1,%2,%3}, [%4];" \
        : "=r"((r)[0]), "=r"((r)[1]), "=r"((r)[2]), "=r"((r)[3]) : "r"(a))
#define LDM4T(r, a) \
    asm volatile("ldmatrix.sync.aligned.m8n8.x4.trans.shared.b16 {%0,%1,%2,%3}, [%4];" \
        : "=r"((r)[0]), "=r"((r)[1]), "=r"((r)[2]), "=r"((r)[3]) : "r"(a))
#define MMA(c, a, b0_, b1_) \
    asm volatile("mma.sync.aligned.m16n8k16.row.col.f32.bf16.bf16.f32 " \
        "{%0,%1,%2,%3}, {%4,%5,%6,%7}, {%8,%9}, {%0,%1,%2,%3};" \
        : "+f"((c)[0]), "+f"((c)[1]), "+f"((c)[2]), "+f"((c)[3]) \
        : "r"((a)[0]), "r"((a)[1]), "r"((a)[2]), "r"((a)[3]), "r"(b0_), "r"(b1_))
#define CP_ASYNC16(dst, src) \
    asm volatile("cp.async.cg.shared.global [%0], [%1], 16;" :: "r"(dst), "l"(src))
#define CP_COMMIT() asm volatile("cp.async.commit_group;" ::: "memory")

// smem geometry.
// MODE 0: 3 full stages of 4 slots (Ah,Al,Bh,Bl) — round-13 proven layout.
// MODE 1/2: A = 2 stages x (hi,lo) slots at base (STS-fed);
//           B = 3 stages x (hi,lo) slots at BOFF (cp.async ring).
// NT tile: 128 rows x 128B, pitch 144.  T tile: 64 rows x 256B, pitch 272.
constexpr int SLOT   = 18432;
constexpr int STG4   = 4 * SLOT;            // MODE0 stage stride (73728)
constexpr int BOFF   = 4 * SLOT;            // MODE1/2 B ring base
constexpr int KOFF   = 10 * SLOT;           // ksm (MODE2) / kred (MODE1): 184320
constexpr int SMEM_MMA = 3 * STG4 + 2048;   // 223232 covers both layouts
constexpr int NPAD = 132;                   // epilogue fp32 row stride

__device__ __forceinline__ void split_store(__nv_bfloat16* hi, __nv_bfloat16* lo,
                                            size_t o, float v) {
    __nv_bfloat16 h = __float2bfloat16(v);
    hi[o] = h;
    lo[o] = __float2bfloat16(v - __bfloat162float(h));
}

// order-independent (deterministic) float atomic max
__device__ __forceinline__ void atomicMaxF(float* addr, float v) {
    if (v >= 0.0f) atomicMax((int*)addr, __float_as_int(v));
    else           atomicMin((u32*)addr, __float_as_uint(v));
}

// ============================================================
// K1 (fused): LayerNorm + diag + bf16 split of DN*xn
//             + proj split + rowmax/bmax init.  Blocks >= 512 do proj.
// ============================================================
__global__ void __launch_bounds__(256) k_pre(const float* __restrict__ x,
                                             const float* __restrict__ gamma,
                                             const float* __restrict__ beta,
                                             const float* __restrict__ proj) {
    const int t = threadIdx.x;
    if (blockIdx.x >= 512) {                 // proj split (32 blocks)
        const int pb = blockIdx.x - 512;
#pragma unroll
        for (int it = 0; it < 8; it++) {
            const int i = pb * 2048 + it * 256 + t;
            split_store(g_pbh, g_pbl, i, proj[i]);
        }
        if (pb == 0 && t < B) g_bmax[t] = __int_as_float(0xFF800000);
        return;
    }
    const int b = blockIdx.x >> 7;           // 128 blocks per batch
    const int s0 = (blockIdx.x & 127) * 32;
    __shared__ float xs[32][257];
    __shared__ float mu_s[32], rs_s[32];
    const float gm = gamma[t], bt = beta[t];
    const int w = t >> 5, lane = t & 31;
#pragma unroll 4
    for (int r = 0; r < 32; r++)
        xs[r][t] = x[((size_t)b * S + s0 + r) * D + t];
    __syncthreads();
#pragma unroll
    for (int rr = 0; rr < 4; rr++) {         // warp w owns rows 4w..4w+3
        const int row = w * 4 + rr;
        float a = 0.f, q = 0.f;
#pragma unroll
        for (int i = 0; i < 8; i++) {
            const float v = xs[row][lane + i * 32];
            a += v; q += v * v;
        }
#pragma unroll
        for (int o = 16; o; o >>= 1) {
            a += __shfl_xor_sync(~0u, a, o);
            q += __shfl_xor_sync(~0u, q, o);
        }
        if (lane == 0) {
            const float mu = a * (1.0f / D);
            mu_s[row] = mu;
            rs_s[row] = rsqrtf(q * (1.0f / D) - mu * mu + LNEPS);
        }
    }
    __syncthreads();
#pragma unroll 4
    for (int r = 0; r < 32; r++) {
        const float xv = (xs[r][t] - mu_s[r]) * rs_s[r] * gm + bt;
        split_store(g_ah, g_al, ((size_t)b * S + s0 + r) * D + t, DN * xv);
        xs[r][t] = xv;
    }
    __syncthreads();
#pragma unroll
    for (int rr = 0; rr < 4; rr++) {         // diag per row
        const int row = w * 4 + rr;
        float q = 0.f;
#pragma unroll
        for (int i = 0; i < 8; i++) {
            const float v = xs[row][lane + i * 32];
            q += v * v;
        }
#pragma unroll
        for (int o = 16; o; o >>= 1) q += __shfl_xor_sync(~0u, q, o);
        if (lane == 0) g_diag[b * S + s0 + row] = q * (0.5f * DN * DN);
    }
    if (t < 32) g_rowmax[b * S + s0 + t] = __int_as_float(0xFF800000);
}

// ============================================================
// Core mma.sync GEMM, 512 threads, 16 warps (32x32 warp tiles on 128x128)
// MODE 0: pd = (DN*xn) @ proj^T      A:NT(cp.async) B:NT(cp.async) + max atomics
// MODE 1: pctx[sk] = k^T @ (DN*xn)   A:T from pd via exp (STS)  B:T(cp.async)
//                                    + pksum column sums (by==0)
// MODE 2: out = dinv * (q @ ctx^T)   A:NT from pd via exp (STS) B:T(cp.async)
//                                    + dinv inline, x8 head broadcast
// ============================================================
template <int MODE>
__global__ void __launch_bounds__(512) k_mma(float* __restrict__ gout) {
    extern __shared__ char sm[];
    const u32 smb = s2u(sm);
    const int t = threadIdx.x, wid = t >> 5, lane = t & 31;
    constexpr int NCH = 4;                 // K = 256 = 4 chunks of 64
    constexpr bool AT = (MODE == 1);
    constexpr bool BT = (MODE != 0);
    constexpr int APITCH = AT ? 272 : 144;

    int b, row0, col0, sk = 0, ldB_;
    size_t bchunk;
    const __nv_bfloat16 *Bh, *Bl;
    const __nv_bfloat16 *A0h = nullptr, *A0l = nullptr;   // MODE0 only
    if constexpr (MODE == 0) {
        b = blockIdx.z; row0 = blockIdx.x * 128; col0 = blockIdx.y * 128;
        A0h = g_ah + ((size_t)b * S + row0) * D;
        A0l = g_al + ((size_t)b * S + row0) * D;
        ldB_ = D; bchunk = 64;
        Bh = g_pbh + (size_t)col0 * D;
        Bl = g_pbl + (size_t)col0 * D;
    } else if constexpr (MODE == 1) {
        b = blockIdx.z / SK; sk = blockIdx.z % SK;
        row0 = blockIdx.x * 128; col0 = blockIdx.y * 128;
        ldB_ = D; bchunk = (size_t)64 * D;
        Bh = g_ah + ((size_t)b * S + sk * 256) * D + col0;   // v = ah [s,d], T
        Bl = g_al + ((size_t)b * S + sk * 256) * D + col0;
    } else {
        b = blockIdx.z; row0 = blockIdx.x * 128; col0 = blockIdx.y * 128;
        ldB_ = D; bchunk = (size_t)64 * D;
        Bh = g_cth + (size_t)b * M * D + col0;               // ctx [m,d], T
        Bl = g_ctl + (size_t)b * M * D + col0;
    }

    float* ksm = (float*)(sm + KOFF);
    if constexpr (MODE == 2) {
        if (t < 256) ksm[t] = g_ksum[b * M + t];
    }

    // ---- A producer state (MODE 1/2: pd -> exp -> bf16 split -> STS) ----
    float4 ra[4];
    float dmv = 0.f, bmaxv = 0.f;
    int ar = 0, ac0 = 0;
    if constexpr (MODE == 1) {
        ar = t >> 3; ac0 = (t & 7) * 16;       // T tile: 64 s-rows x 128 m
        bmaxv = g_bmax[b];
    } else if constexpr (MODE == 2) {
        ar = t >> 2; ac0 = (t & 3) * 16;       // NT tile: 128 s-rows x 64 m
        const int s = row0 + ar;
        dmv = g_diag[b * S + s] + g_rowmax[b * S + s];
    }
    auto ldg_A = [&](int ch) {
        const float* src;
        if constexpr (MODE == 1) {
            const int s = sk * 256 + ch * 64 + ar;
            src = g_pd + ((size_t)b * S + s) * M + row0 + ac0;
            dmv = g_diag[b * S + s] + bmaxv;
        } else {
            src = g_pd + ((size_t)b * S + row0 + ar) * M + ch * 64 + ac0;
        }
        ra[0] = *(const float4*)(src);
        ra[1] = *(const float4*)(src + 4);
        ra[2] = *(const float4*)(src + 8);
        ra[3] = *(const float4*)(src + 12);
    };
    auto sts_A = [&](int at) {
        __nv_bfloat16 h16[16], l16[16];
#pragma unroll
        for (int i = 0; i < 4; i++) {
            const float* v = (const float*)&ra[i];
#pragma unroll
            for (int j = 0; j < 4; j++) {
                const float e = RATIO * __expf(v[j] - dmv) + RKEPS;
                const __nv_bfloat16 hh = __float2bfloat16(e);
                h16[i * 4 + j] = hh;
                l16[i * 4 + j] = __float2bfloat16(e - __bfloat162float(hh));
            }
        }
        char* ph = sm + at * 2 * SLOT + ar * APITCH + ac0 * 2;
        ((uint4*)ph)[0] = ((const uint4*)h16)[0];
        ((uint4*)ph)[1] = ((const uint4*)h16)[1];
        char* pl = ph + SLOT;
        ((uint4*)pl)[0] = ((const uint4*)l16)[0];
        ((uint4*)pl)[1] = ((const uint4*)l16)[1];
    };

    // ---- B (and MODE0 A) cp.async loaders ----
    auto load_tile = [&](const __nv_bfloat16* src, int ld, u32 dst, bool tr) {
#pragma unroll
        for (int it = 0; it < 2; it++) {
            const int idx = it * 512 + t;
            if (!tr) {
                const int r = idx >> 3, c = idx & 7;
                CP_ASYNC16(dst + r * 144 + c * 16, src + (size_t)r * ld + c * 8);
            } else {
                const int r = idx >> 4, c = idx & 15;
                CP_ASYNC16(dst + r * 272 + c * 16, src + (size_t)r * ld + c * 8);
            }
        }
    };
    auto load_stage = [&](int ch, int st) {
        if constexpr (MODE == 0) {
            const u32 base = smb + st * STG4;
            load_tile(A0h + ch * 64, D, base,            false);
            load_tile(A0l + ch * 64, D, base + SLOT,     false);
            load_tile(Bh + ch * bchunk, ldB_, base + 2 * SLOT, false);
            load_tile(Bl + ch * bchunk, ldB_, base + 3 * SLOT, false);
        } else {
            const u32 base = smb + BOFF + st * 2 * SLOT;
            load_tile(Bh + ch * bchunk, ldB_, base,        BT);
            load_tile(Bl + ch * bchunk, ldB_, base + SLOT, BT);
        }
        CP_COMMIT();
    };

    if constexpr (MODE >= 1) ldg_A(0);
    load_stage(0, 0);
    load_stage(1, 1);

    const int wm = wid >> 2, wn = wid & 3;     // warp tile 32(m) x 32(n)
    const u32 aoff_nt = (u32)((lane & 15) * 144 + (lane >> 4) * 16);
    const u32 boff_nt = (u32)(((lane & 7) + ((lane >> 4) & 1) * 8) * 144 +
                              ((lane >> 3) & 1) * 16);
    const u32 aoff_t = (u32)(((lane & 7) + ((lane >> 4) & 1) * 8) * 272 +
                             ((lane >> 3) & 1) * 16);
    const u32 boff_t = (u32)(((lane & 7) + ((lane >> 3) & 1) * 8) * 272 +
                             ((lane >> 4) & 1) * 16);

    float acc[2][4][4] = {};
    float dacc = 0.f, kspart = 0.f;
    const int drow = t >> 2, dcs = (t & 3) * 16;   // dinv map (MODE 2)
    const int km = t & 127, ksq = t >> 7;          // pksum map (MODE 1)

#pragma unroll
    for (int ch = 0; ch < NCH; ch++) {
        const int st = ch % 3, at = ch & 1;
        if constexpr (MODE >= 1) {
            sts_A(at);                       // chunk ch into A ring
            if (ch + 1 < NCH) ldg_A(ch + 1); // prefetch next
        }
        if (ch + 2 < NCH) load_stage(ch + 2, (ch + 2) % 3);
        if (ch < 2)      asm volatile("cp.async.wait_group 2;" ::: "memory");
        else if (ch == 2) asm volatile("cp.async.wait_group 1;" ::: "memory");
        else              asm volatile("cp.async.wait_group 0;" ::: "memory");
        __syncthreads();

        u32 sAh, sAl, sBh, sBl;
        if constexpr (MODE == 0) {
            const u32 sA = smb + st * STG4;
            sAh = sA; sAl = sA + SLOT; sBh = sA + 2 * SLOT; sBl = sA + 3 * SLOT;
        } else {
            sAh = smb + at * 2 * SLOT; sAl = sAh + SLOT;
            sBh = smb + BOFF + st * 2 * SLOT; sBl = sBh + SLOT;
        }
#pragma unroll
        for (int ks = 0; ks < 4; ks++) {
            u32 ah[2][4], al[2][4], bh[2][4], bl[2][4];
#pragma unroll
            for (int mi = 0; mi < 2; mi++) {
                if constexpr (!AT) {
                    const u32 a = (u32)((wm * 32 + mi * 16) * 144 + ks * 32) + aoff_nt;
                    LDM4(ah[mi], sAh + a);
                    LDM4(al[mi], sAl + a);
                } else {
                    const u32 a = (u32)(ks * 16 * 272 + (wm * 32 + mi * 16) * 2) + aoff_t;
                    LDM4T(ah[mi], sAh + a);
                    LDM4T(al[mi], sAl + a);
                }
            }
#pragma unroll
            for (int g = 0; g < 2; g++) {
                if constexpr (!BT) {
                    const u32 a = (u32)((wn * 32 + g * 16) * 144 + ks * 32) + boff_nt;
                    LDM4(bh[g], sBh + a);
                    LDM4(bl[g], sBl + a);
                } else {
                    const u32 a = (u32)(ks * 16 * 272 + (wn * 32 + g * 16) * 2) + boff_t;
                    LDM4T(bh[g], sBh + a);
                    LDM4T(bl[g], sBl + a);
                }
            }
#pragma unroll
            for (int mi = 0; mi < 2; mi++)
#pragma unroll
                for (int g = 0; g < 2; g++) {
                    MMA(acc[mi][2 * g],     ah[mi], bh[g][0], bh[g][1]);
                    MMA(acc[mi][2 * g + 1], ah[mi], bh[g][2], bh[g][3]);
                    MMA(acc[mi][2 * g],     ah[mi], bl[g][0], bl[g][1]);
                    MMA(acc[mi][2 * g + 1], ah[mi], bl[g][2], bl[g][3]);
                    MMA(acc[mi][2 * g],     al[mi], bh[g][0], bh[g][1]);
                    MMA(acc[mi][2 * g + 1], al[mi], bh[g][2], bh[g][3]);
                }
        }
        if constexpr (MODE == 2) {
            // partial dot(q[drow,:], ksum) from staged q tiles (NT, pitch 144)
            const __nv_bfloat16* qh =
                (const __nv_bfloat16*)(sm + at * 2 * SLOT + drow * 144) + dcs;
            const __nv_bfloat16* ql = (const __nv_bfloat16*)((const char*)qh + SLOT);
            const float* kv = ksm + ch * 64 + dcs;
#pragma unroll
            for (int j = 0; j < 16; j++)
                dacc += (__bfloat162float(qh[j]) + __bfloat162float(ql[j])) * kv[j];
        }
        if constexpr (MODE == 1) {
            if (blockIdx.y == 0) {
                // column sums of k tile (T, pitch 272): thread owns column km,
                // quarter ksq of the 64 s-rows.
#pragma unroll
                for (int si = 0; si < 16; si++) {
                    const char* base = sm + at * 2 * SLOT + (ksq * 16 + si) * 272;
                    kspart += __bfloat162float(((const __nv_bfloat16*)base)[km]) +
                              __bfloat162float(((const __nv_bfloat16*)(base + SLOT))[km]);
                }
            }
        }
        __syncthreads();
    }

    float dv_val = 1.0f;
    if constexpr (MODE == 2) {
        dacc += __shfl_xor_sync(~0u, dacc, 1);
        dacc += __shfl_xor_sync(~0u, dacc, 2);
        dv_val = 1.0f / dacc;                  // valid for row = t>>2
    }
    if constexpr (MODE == 1) {
        if (blockIdx.y == 0) ((float*)(sm + KOFF))[ksq * 128 + km] = kspart;
    }

    // Epilogue: fragments -> smem (fp32, NPAD stride) -> coalesced stores
    float* ep = (float*)sm;
#pragma unroll
    for (int mi = 0; mi < 2; mi++)
#pragma unroll
        for (int g = 0; g < 4; g++) {
            const int row = wm * 32 + mi * 16 + (lane >> 2);
            const int col = wn * 32 + g * 8 + (lane & 3) * 2;
            *(float2*)&ep[row * NPAD + col] =
                make_float2(acc[mi][g][0], acc[mi][g][1]);
            *(float2*)&ep[(row + 8) * NPAD + col] =
                make_float2(acc[mi][g][2], acc[mi][g][3]);
        }
    __syncthreads();

    const int row = t >> 2, c0 = (t & 3) * 32;   // 32 cols per thread
    const float* er = ep + row * NPAD + c0;
    if constexpr (MODE == 0) {
        float mx = -1e30f;
        const size_t o = ((size_t)b * S + row0 + row) * M + col0 + c0;
#pragma unroll
        for (int j = 0; j < 8; j++) {
            const float4 v = *(const float4*)(er + j * 4);
            mx = fmaxf(mx, fmaxf(fmaxf(v.x, v.y), fmaxf(v.z, v.w)));
            *(float4*)(g_pd + o + j * 4) = v;
        }
        mx = fmaxf(mx, __shfl_xor_sync(~0u, mx, 1));
        mx = fmaxf(mx, __shfl_xor_sync(~0u, mx, 2));  // full 128-col tile max
        if ((t & 3) == 0) atomicMaxF(&g_rowmax[b * S + row0 + row], mx);
        float bmx = mx;
#pragma unroll
        for (int o2 = 16; o2; o2 >>= 1)
            bmx = fmaxf(bmx, __shfl_xor_sync(~0u, bmx, o2));
        __shared__ float wred[16];
        if (lane == 0) wred[wid] = bmx;
        __syncthreads();
        if (t == 0) {
            float m2 = wred[0];
#pragma unroll
            for (int i = 1; i < 16; i++) m2 = fmaxf(m2, wred[i]);
            atomicMaxF(&g_bmax[b], m2);
        }
    } else if constexpr (MODE == 1) {
        const size_t o =
            (((size_t)(b * SK + sk)) * M + row0 + row) * D + col0 + c0;
#pragma unroll
        for (int j = 0; j < 8; j++)
            __stcs((float4*)(g_pctx + o + j * 4), *(const float4*)(er + j * 4));
        if (blockIdx.y == 0 && t < 128) {      // pksum: kred reduced post-barrier
            const float* kred = (const float*)(sm + KOFF);
            g_pksum[(size_t)(b * SK + sk) * M + row0 + t] =
                kred[t] + kred[128 + t] + kred[256 + t] + kred[384 + t];
        }
    } else {
        const size_t o = ((size_t)b * H * S + row0 + row) * D + col0 + c0;
#pragma unroll
        for (int j = 0; j < 8; j++) {
            float4 v = *(const float4*)(er + j * 4);
            v.x *= dv_val; v.y *= dv_val; v.z *= dv_val; v.w *= dv_val;
#pragma unroll
            for (int h = 0; h < H; h++)
                __stcs((float4*)(gout + o + (size_t)h * S * D + j * 4), v);
        }
    }
}

// ============================================================
// K4: reduce ctx partials (x4 = 1/DN scale) -> bf16 split ctx [m,d]
//     + ksum reduction (block 0 of each batch).
// ============================================================
__global__ void __launch_bounds__(256) k_ctxred() {
    const int b = blockIdx.y;
    const int idx4 = blockIdx.x * 256 + threadIdx.x;    // float4 index, 0..16383
    const float4* src = (const float4*)g_pctx + (size_t)b * SK * 16384 + idx4;
    float4 s = make_float4(0.f, 0.f, 0.f, 0.f);
#pragma unroll
    for (int sk = 0; sk < SK; sk++) {
        const float4 p = __ldcs(src + (size_t)sk * 16384);
        s.x += p.x; s.y += p.y; s.z += p.z; s.w += p.w;
    }
    const size_t o = (size_t)b * M * D + idx4 * 4;
    split_store(g_cth, g_ctl, o + 0, s.x * 4.0f);
    split_store(g_cth, g_ctl, o + 1, s.y * 4.0f);
    split_store(g_cth, g_ctl, o + 2, s.z * 4.0f);
    split_store(g_cth, g_ctl, o + 3, s.w * 4.0f);
    if (blockIdx.x == 0) {                   // ksum: 256 threads = 256 m-cols
        float ks = 0.f;
#pragma unroll
        for (int sk = 0; sk < SK; sk++)
            ks += g_pksum[(size_t)(b * SK + sk) * M + threadIdx.x];
        g_ksum[b * M + threadIdx.x] = ks;
    }
}

extern "C" void kernel_launch(void* const* d_in, const int* in_sizes, int n_in,
                              void* d_out, int out_size) {
    const float* x     = (const float*)d_in[0];
    const float* gamma = (const float*)d_in[1];
    const float* beta  = (const float*)d_in[2];
    const float* proj  = (const float*)d_in[3];
    float* out = (float*)d_out;
    (void)in_sizes; (void)n_in; (void)out_size;

    cudaFuncSetAttribute(k_mma<0>, cudaFuncAttributeMaxDynamicSharedMemorySize, SMEM_MMA);
    cudaFuncSetAttribute(k_mma<1>, cudaFuncAttributeMaxDynamicSharedMemorySize, SMEM_MMA);
    cudaFuncSetAttribute(k_mma<2>, cudaFuncAttributeMaxDynamicSharedMemorySize, SMEM_MMA);

    k_pre<<<544, 256>>>(x, gamma, beta, proj);
    k_mma<0><<<dim3(S / 128, M / 128, B), 512, SMEM_MMA>>>(nullptr);
    k_mma<1><<<dim3(M / 128, D / 128, B * SK), 512, SMEM_MMA>>>(nullptr);
    k_ctxred<<<dim3(64, B), 256>>>();
    k_mma<2><<<dim3(S / 128, D / 128, B), 512, SMEM_MMA>>>(out);
}

// round 15
// speedup vs baseline: 1.8958x; 1.8958x over previous
#include <cuda_runtime.h>
#include <cuda_bf16.h>

using u32 = unsigned int;
using u64 = unsigned long long;

// Problem constants (fixed by setup_inputs)
constexpr int B = 4, S = 4096, D = 256, M = 256, H = 8;
constexpr int SK = 16;                  // split-K chunks for ctx GEMM
constexpr float LNEPS = 1e-5f;
constexpr float KEPS  = 1e-4f;
constexpr float DN    = 0.25f;          // 256^-0.25
constexpr float RATIO = 0.0625f;        // 256^-0.5
constexpr float RKEPS = RATIO * KEPS;

// ---------------- device scratch (no allocation APIs allowed) --------------
__device__ float g_diag[B * S];
__device__ __nv_bfloat16 g_ah[B * S * D], g_al[B * S * D];   // split(DN*xn) [s,d]
__device__ __nv_bfloat16 g_pbh[M * D],   g_pbl[M * D];       // split(proj)  [m,d]
__device__ float g_pd[B * S * M];                 // projection, fp32
__device__ float g_rowmax[B * S];                 // atomicMax targets
__device__ float g_bmax[B];
__device__ float g_pksum[B * SK * M];
__device__ float g_ksum[B * M];
__device__ float g_pctx[B * SK * M * D];          // split-K ctx partials (DN-scaled)
__device__ __nv_bfloat16 g_cth[B * M * D], g_ctl[B * M * D]; // split(ctx) [m,d]

// ---------------- PTX helpers (plain sm_103-safe: mma.sync/ldmatrix/cp.async)
__device__ __forceinline__ u32 s2u(const void* p) {
    u32 a;
    asm("{ .reg .u64 t; cvta.to.shared.u64 t, %1; cvt.u32.u64 %0, t; }"
        : "=r"(a) : "l"(p));
    return a;
}
#define LDM4(r, a) \
    asm volatile("ldmatrix.sync.aligned.m8n8.x4.shared.b16 {%0,%1,%2,%3}, [%4];" \
        : "=r"((r)[0]), "=r"((r)[1]), "=r"((r)[2]), "=r"((r)[3]) : "r"(a))
#define LDM4T(r, a) \
    asm volatile("ldmatrix.sync.aligned.m8n8.x4.trans.shared.b16 {%0,%1,%2,%3}, [%4];" \
        : "=r"((r)[0]), "=r"((r)[1]), "=r"((r)[2]), "=r"((r)[3]) : "r"(a))
#define MMA(c, a, b0_, b1_) \
    asm volatile("mma.sync.aligned.m16n8k16.row.col.f32.bf16.bf16.f32 " \
        "{%0,%1,%2,%3}, {%4,%5,%6,%7}, {%8,%9}, {%0,%1,%2,%3};" \
        : "+f"((c)[0]), "+f"((c)[1]), "+f"((c)[2]), "+f"((c)[3]) \
        : "r"((a)[0]), "r"((a)[1]), "r"((a)[2]), "r"((a)[3]), "r"(b0_), "r"(b1_))
#define CP_ASYNC16(dst, src) \
    asm volatile("cp.async.cg.shared.global [%0], [%1], 16;" :: "r"(dst), "l"(src))
#define CP_COMMIT() asm volatile("cp.async.commit_group;" ::: "memory")

// smem geometry.
// MODE 0: 3 full stages of 4 slots (Ah,Al,Bh,Bl).
// MODE 1/2: A = 2 stages x (hi,lo) slots at base (STS-fed);
//           B = 3 stages x (hi,lo) slots at BOFF (cp.async ring).
// NT tile: 128 rows x 128B, pitch 144.  T tile: 64 rows x 256B, pitch 272.
constexpr int SLOT   = 18432;
constexpr int STG4   = 4 * SLOT;            // MODE0 stage stride (73728)
constexpr int BOFF   = 4 * SLOT;            // MODE1/2 B ring base
constexpr int KOFF   = 10 * SLOT;           // ksm/kred base: 184320
constexpr int DINV_OFF = KOFF + 1024;       // dinv_s[128] (MODE 2)
constexpr int SMEM_MMA = 3 * STG4 + 2048;   // 223232 covers both layouts
constexpr int NPAD = 132;                   // epilogue fp32 row stride

__device__ __forceinline__ void split_store(__nv_bfloat16* hi, __nv_bfloat16* lo,
                                            size_t o, float v) {
    __nv_bfloat16 h = __float2bfloat16(v);
    hi[o] = h;
    lo[o] = __float2bfloat16(v - __bfloat162float(h));
}

// order-independent (deterministic) float atomic max
__device__ __forceinline__ void atomicMaxF(float* addr, float v) {
    if (v >= 0.0f) atomicMax((int*)addr, __float_as_int(v));
    else           atomicMin((u32*)addr, __float_as_uint(v));
}

// ============================================================
// K1 (fused): LayerNorm + diag + bf16 split of DN*xn
//             + proj split + rowmax/bmax init.  Blocks >= 512 do proj.
// ============================================================
__global__ void __launch_bounds__(256) k_pre(const float* __restrict__ x,
                                             const float* __restrict__ gamma,
                                             const float* __restrict__ beta,
                                             const float* __restrict__ proj) {
    const int t = threadIdx.x;
    if (blockIdx.x >= 512) {                 // proj split (32 blocks)
        const int pb = blockIdx.x - 512;
#pragma unroll
        for (int it = 0; it < 8; it++) {
            const int i = pb * 2048 + it * 256 + t;
            split_store(g_pbh, g_pbl, i, proj[i]);
        }
        if (pb == 0 && t < B) g_bmax[t] = __int_as_float(0xFF800000);
        return;
    }
    const int b = blockIdx.x >> 7;           // 128 blocks per batch
    const int s0 = (blockIdx.x & 127) * 32;
    __shared__ float xs[32][257];
    __shared__ float mu_s[32], rs_s[32];
    const float gm = gamma[t], bt = beta[t];
    const int w = t >> 5, lane = t & 31;
#pragma unroll 4
    for (int r = 0; r < 32; r++)
        xs[r][t] = x[((size_t)b * S + s0 + r) * D + t];
    __syncthreads();
#pragma unroll
    for (int rr = 0; rr < 4; rr++) {         // warp w owns rows 4w..4w+3
        const int row = w * 4 + rr;
        float a = 0.f, q = 0.f;
#pragma unroll
        for (int i = 0; i < 8; i++) {
            const float v = xs[row][lane + i * 32];
            a += v; q += v * v;
        }
#pragma unroll
        for (int o = 16; o; o >>= 1) {
            a += __shfl_xor_sync(~0u, a, o);
            q += __shfl_xor_sync(~0u, q, o);
        }
        if (lane == 0) {
            const float mu = a * (1.0f / D);
            mu_s[row] = mu;
            rs_s[row] = rsqrtf(q * (1.0f / D) - mu * mu + LNEPS);
        }
    }
    __syncthreads();
#pragma unroll 4
    for (int r = 0; r < 32; r++) {
        const float xv = (xs[r][t] - mu_s[r]) * rs_s[r] * gm + bt;
        split_store(g_ah, g_al, ((size_t)b * S + s0 + r) * D + t, DN * xv);
        xs[r][t] = xv;
    }
    __syncthreads();
#pragma unroll
    for (int rr = 0; rr < 4; rr++) {         // diag per row
        const int row = w * 4 + rr;
        float q = 0.f;
#pragma unroll
        for (int i = 0; i < 8; i++) {
            const float v = xs[row][lane + i * 32];
            q += v * v;
        }
#pragma unroll
        for (int o = 16; o; o >>= 1) q += __shfl_xor_sync(~0u, q, o);
        if (lane == 0) g_diag[b * S + s0 + row] = q * (0.5f * DN * DN);
    }
    if (t < 32) g_rowmax[b * S + s0 + t] = __int_as_float(0xFF800000);
}

// ============================================================
// Core mma.sync GEMM, 512 threads, 16 warps (32x32 warp tiles on 128x128)
// MODE 0: pd = (DN*xn) @ proj^T      A:NT(cp.async) B:NT(cp.async) + max atomics
// MODE 1: pctx[sk] = k^T @ (DN*xn)   A:T from pd via exp (STS)  B:T(cp.async)
//                                    + pksum column sums (by==0)
// MODE 2: out = dinv * (q @ ctx^T)   A:NT from pd via exp (STS) B:T(cp.async)
//                                    + dinv inline, x8 head broadcast
// Epilogue stores: warp-per-row (each store = 512B contiguous).
// ============================================================
template <int MODE>
__global__ void __launch_bounds__(512) k_mma(float* __restrict__ gout) {
    extern __shared__ char sm[];
    const u32 smb = s2u(sm);
    const int t = threadIdx.x, wid = t >> 5, lane = t & 31;
    constexpr int NCH = 4;                 // K = 256 = 4 chunks of 64
    constexpr bool AT = (MODE == 1);
    constexpr bool BT = (MODE != 0);
    constexpr int APITCH = AT ? 272 : 144;

    int b, row0, col0, sk = 0, ldB_;
    size_t bchunk;
    const __nv_bfloat16 *Bh, *Bl;
    const __nv_bfloat16 *A0h = nullptr, *A0l = nullptr;   // MODE0 only
    if constexpr (MODE == 0) {
        b = blockIdx.z; row0 = blockIdx.x * 128; col0 = blockIdx.y * 128;
        A0h = g_ah + ((size_t)b * S + row0) * D;
        A0l = g_al + ((size_t)b * S + row0) * D;
        ldB_ = D; bchunk = 64;
        Bh = g_pbh + (size_t)col0 * D;
        Bl = g_pbl + (size_t)col0 * D;
    } else if constexpr (MODE == 1) {
        b = blockIdx.z / SK; sk = blockIdx.z % SK;
        row0 = blockIdx.x * 128; col0 = blockIdx.y * 128;
        ldB_ = D; bchunk = (size_t)64 * D;
        Bh = g_ah + ((size_t)b * S + sk * 256) * D + col0;   // v = ah [s,d], T
        Bl = g_al + ((size_t)b * S + sk * 256) * D + col0;
    } else {
        b = blockIdx.z; row0 = blockIdx.x * 128; col0 = blockIdx.y * 128;
        ldB_ = D; bchunk = (size_t)64 * D;
        Bh = g_cth + (size_t)b * M * D + col0;               // ctx [m,d], T
        Bl = g_ctl + (size_t)b * M * D + col0;
    }

    float* ksm = (float*)(sm + KOFF);
    if constexpr (MODE == 2) {
        if (t < 256) ksm[t] = g_ksum[b * M + t];
    }

    // ---- A producer state (MODE 1/2: pd -> exp -> bf16 split -> STS) ----
    float4 ra[4];
    float dmv = 0.f, bmaxv = 0.f;
    int ar = 0, ac0 = 0;
    if constexpr (MODE == 1) {
        ar = t >> 3; ac0 = (t & 7) * 16;       // T tile: 64 s-rows x 128 m
        bmaxv = g_bmax[b];
    } else if constexpr (MODE == 2) {
        ar = t >> 2; ac0 = (t & 3) * 16;       // NT tile: 128 s-rows x 64 m
        const int s = row0 + ar;
        dmv = g_diag[b * S + s] + g_rowmax[b * S + s];
    }
    auto ldg_A = [&](int ch) {
        const float* src;
        if constexpr (MODE == 1) {
            const int s = sk * 256 + ch * 64 + ar;
            src = g_pd + ((size_t)b * S + s) * M + row0 + ac0;
            dmv = g_diag[b * S + s] + bmaxv;
        } else {
            src = g_pd + ((size_t)b * S + row0 + ar) * M + ch * 64 + ac0;
        }
        ra[0] = *(const float4*)(src);
        ra[1] = *(const float4*)(src + 4);
        ra[2] = *(const float4*)(src + 8);
        ra[3] = *(const float4*)(src + 12);
    };
    auto sts_A = [&](int at) {
        __nv_bfloat16 h16[16], l16[16];
#pragma unroll
        for (int i = 0; i < 4; i++) {
            const float* v = (const float*)&ra[i];
#pragma unroll
            for (int j = 0; j < 4; j++) {
                const float e = RATIO * __expf(v[j] - dmv) + RKEPS;
                const __nv_bfloat16 hh = __float2bfloat16(e);
                h16[i * 4 + j] = hh;
                l16[i * 4 + j] = __float2bfloat16(e - __bfloat162float(hh));
            }
        }
        char* ph = sm + at * 2 * SLOT + ar * APITCH + ac0 * 2;
        ((uint4*)ph)[0] = ((const uint4*)h16)[0];
        ((uint4*)ph)[1] = ((const uint4*)h16)[1];
        char* pl = ph + SLOT;
        ((uint4*)pl)[0] = ((const uint4*)l16)[0];
        ((uint4*)pl)[1] = ((const uint4*)l16)[1];
    };

    // ---- B (and MODE0 A) cp.async loaders ----
    auto load_tile = [&](const __nv_bfloat16* src, int ld, u32 dst, bool tr) {
#pragma unroll
        for (int it = 0; it < 2; it++) {
            const int idx = it * 512 + t;
            if (!tr) {
                const int r = idx >> 3, c = idx & 7;
                CP_ASYNC16(dst + r * 144 + c * 16, src + (size_t)r * ld + c * 8);
            } else {
                const int r = idx >> 4, c = idx & 15;
                CP_ASYNC16(dst + r * 272 + c * 16, src + (size_t)r * ld + c * 8);
            }
        }
    };
    auto load_stage = [&](int ch, int st) {
        if constexpr (MODE == 0) {
            const u32 base = smb + st * STG4;
            load_tile(A0h + ch * 64, D, base,            false);
            load_tile(A0l + ch * 64, D, base + SLOT,     false);
            load_tile(Bh + ch * bchunk, ldB_, base + 2 * SLOT, false);
            load_tile(Bl + ch * bchunk, ldB_, base + 3 * SLOT, false);
        } else {
            const u32 base = smb + BOFF + st * 2 * SLOT;
            load_tile(Bh + ch * bchunk, ldB_, base,        BT);
            load_tile(Bl + ch * bchunk, ldB_, base + SLOT, BT);
        }
        CP_COMMIT();
    };

    if constexpr (MODE >= 1) ldg_A(0);
    load_stage(0, 0);
    load_stage(1, 1);

    const int wm = wid >> 2, wn = wid & 3;     // warp tile 32(m) x 32(n)
    const u32 aoff_nt = (u32)((lane & 15) * 144 + (lane >> 4) * 16);
    const u32 boff_nt = (u32)(((lane & 7) + ((lane >> 4) & 1) * 8) * 144 +
                              ((lane >> 3) & 1) * 16);
    const u32 aoff_t = (u32)(((lane & 7) + ((lane >> 4) & 1) * 8) * 272 +
                             ((lane >> 3) & 1) * 16);
    const u32 boff_t = (u32)(((lane & 7) + ((lane >> 3) & 1) * 8) * 272 +
                             ((lane >> 4) & 1) * 16);

    float acc[2][4][4] = {};
    float dacc = 0.f, kspart = 0.f;
    const int drow = t >> 2, dcs = (t & 3) * 16;   // dinv map (MODE 2)
    const int km = t & 127, ksq = t >> 7;          // pksum map (MODE 1)

#pragma unroll
    for (int ch = 0; ch < NCH; ch++) {
        const int st = ch % 3, at = ch & 1;
        if constexpr (MODE >= 1) {
            sts_A(at);                       // chunk ch into A ring
            if (ch + 1 < NCH) ldg_A(ch + 1); // prefetch next
        }
        if (ch + 2 < NCH) load_stage(ch + 2, (ch + 2) % 3);
        if (ch < 2)      asm volatile("cp.async.wait_group 2;" ::: "memory");
        else if (ch == 2) asm volatile("cp.async.wait_group 1;" ::: "memory");
        else              asm volatile("cp.async.wait_group 0;" ::: "memory");
        __syncthreads();

        u32 sAh, sAl, sBh, sBl;
        if constexpr (MODE == 0) {
            const u32 sA = smb + st * STG4;
            sAh = sA; sAl = sA + SLOT; sBh = sA + 2 * SLOT; sBl = sA + 3 * SLOT;
        } else {
            sAh = smb + at * 2 * SLOT; sAl = sAh + SLOT;
            sBh = smb + BOFF + st * 2 * SLOT; sBl = sBh + SLOT;
        }
#pragma unroll
        for (int ks = 0; ks < 4; ks++) {
            u32 ah[2][4], al[2][4], bh[2][4], bl[2][4];
#pragma unroll
            for (int mi = 0; mi < 2; mi++) {
                if constexpr (!AT) {
                    const u32 a = (u32)((wm * 32 + mi * 16) * 144 + ks * 32) + aoff_nt;
                    LDM4(ah[mi], sAh + a);
                    LDM4(al[mi], sAl + a);
                } else {
                    const u32 a = (u32)(ks * 16 * 272 + (wm * 32 + mi * 16) * 2) + aoff_t;
                    LDM4T(ah[mi], sAh + a);
                    LDM4T(al[mi], sAl + a);
                }
            }
#pragma unroll
            for (int g = 0; g < 2; g++) {
                if constexpr (!BT) {
                    const u32 a = (u32)((wn * 32 + g * 16) * 144 + ks * 32) + boff_nt;
                    LDM4(bh[g], sBh + a);
                    LDM4(bl[g], sBl + a);
                } else {
                    const u32 a = (u32)(ks * 16 * 272 + (wn * 32 + g * 16) * 2) + boff_t;
                    LDM4T(bh[g], sBh + a);
                    LDM4T(bl[g], sBl + a);
                }
            }
#pragma unroll
            for (int mi = 0; mi < 2; mi++)
#pragma unroll
                for (int g = 0; g < 2; g++) {
                    MMA(acc[mi][2 * g],     ah[mi], bh[g][0], bh[g][1]);
                    MMA(acc[mi][2 * g + 1], ah[mi], bh[g][2], bh[g][3]);
                    MMA(acc[mi][2 * g],     ah[mi], bl[g][0], bl[g][1]);
                    MMA(acc[mi][2 * g + 1], ah[mi], bl[g][2], bl[g][3]);
                    MMA(acc[mi][2 * g],     al[mi], bh[g][0], bh[g][1]);
                    MMA(acc[mi][2 * g + 1], al[mi], bh[g][2], bh[g][3]);
                }
        }
        if constexpr (MODE == 2) {
            // partial dot(q[drow,:], ksum) from staged q tiles (NT, pitch 144)
            const __nv_bfloat16* qh =
                (const __nv_bfloat16*)(sm + at * 2 * SLOT + drow * 144) + dcs;
            const __nv_bfloat16* ql = (const __nv_bfloat16*)((const char*)qh + SLOT);
            const float* kv = ksm + ch * 64 + dcs;
#pragma unroll
            for (int j = 0; j < 16; j++)
                dacc += (__bfloat162float(qh[j]) + __bfloat162float(ql[j])) * kv[j];
        }
        if constexpr (MODE == 1) {
            if (blockIdx.y == 0) {
                // column sums of k tile (T, pitch 272): thread owns column km,
                // quarter ksq of the 64 s-rows.
#pragma unroll
                for (int si = 0; si < 16; si++) {
                    const char* base = sm + at * 2 * SLOT + (ksq * 16 + si) * 272;
                    kspart += __bfloat162float(((const __nv_bfloat16*)base)[km]) +
                              __bfloat162float(((const __nv_bfloat16*)(base + SLOT))[km]);
                }
            }
        }
        __syncthreads();
    }

    if constexpr (MODE == 2) {
        dacc += __shfl_xor_sync(~0u, dacc, 1);
        dacc += __shfl_xor_sync(~0u, dacc, 2);
        if ((t & 3) == 0)                          // publish dinv per row
            ((float*)(sm + DINV_OFF))[drow] = 1.0f / dacc;
    }
    if constexpr (MODE == 1) {
        if (blockIdx.y == 0) ((float*)(sm + KOFF))[ksq * 128 + km] = kspart;
    }

    // Epilogue: fragments -> smem (fp32, NPAD stride) -> warp-per-row stores
    float* ep = (float*)sm;
#pragma unroll
    for (int mi = 0; mi < 2; mi++)
#pragma unroll
        for (int g = 0; g < 4; g++) {
            const int row = wm * 32 + mi * 16 + (lane >> 2);
            const int col = wn * 32 + g * 8 + (lane & 3) * 2;
            *(float2*)&ep[row * NPAD + col] =
                make_float2(acc[mi][g][0], acc[mi][g][1]);
            *(float2*)&ep[(row + 8) * NPAD + col] =
                make_float2(acc[mi][g][2], acc[mi][g][3]);
        }
    __syncthreads();

    // warp wid owns rows 8*wid .. 8*wid+7; lane owns float4 `lane` of the row.
    if constexpr (MODE == 0) {
        float bmx = -1e30f;
#pragma unroll
        for (int j = 0; j < 8; j++) {
            const int row = wid * 8 + j;
            const float4 v = *(const float4*)&ep[row * NPAD + lane * 4];
            float mx = fmaxf(fmaxf(v.x, v.y), fmaxf(v.z, v.w));
#pragma unroll
            for (int o2 = 16; o2; o2 >>= 1)
                mx = fmaxf(mx, __shfl_xor_sync(~0u, mx, o2));
            if (lane == 0) atomicMaxF(&g_rowmax[b * S + row0 + row], mx);
            bmx = fmaxf(bmx, mx);
            *(float4*)(g_pd + ((size_t)b * S + row0 + row) * M + col0 + lane * 4) = v;
        }
        __shared__ float wred[16];
        if (lane == 0) wred[wid] = bmx;
        __syncthreads();
        if (t == 0) {
            float m2 = wred[0];
#pragma unroll
            for (int i = 1; i < 16; i++) m2 = fmaxf(m2, wred[i]);
            atomicMaxF(&g_bmax[b], m2);
        }
    } else if constexpr (MODE == 1) {
#pragma unroll
        for (int j = 0; j < 8; j++) {
            const int row = wid * 8 + j;
            const float4 v = *(const float4*)&ep[row * NPAD + lane * 4];
            __stcs((float4*)(g_pctx +
                (((size_t)(b * SK + sk)) * M + row0 + row) * D + col0 + lane * 4), v);
        }
        if (blockIdx.y == 0 && t < 128) {      // pksum: kred reduced post-barrier
            const float* kred = (const float*)(sm + KOFF);
            g_pksum[(size_t)(b * SK + sk) * M + row0 + t] =
                kred[t] + kred[128 + t] + kred[256 + t] + kred[384 + t];
        }
    } else {
        const float* dinv_s = (const float*)(sm + DINV_OFF);
#pragma unroll
        for (int j = 0; j < 8; j++) {
            const int row = wid * 8 + j;
            const float dv = dinv_s[row];
            float4 v = *(const float4*)&ep[row * NPAD + lane * 4];
            v.x *= dv; v.y *= dv; v.z *= dv; v.w *= dv;
            const size_t o = ((size_t)b * H * S + row0 + row) * D + col0 + lane * 4;
#pragma unroll
            for (int h = 0; h < H; h++)
                __stcs((float4*)(gout + o + (size_t)h * S * D), v);
        }
    }
}

// ============================================================
// K4: reduce ctx partials (x4 = 1/DN scale) -> bf16 split ctx [m,d]
//     + ksum reduction (block 0 of each batch).
// ============================================================
__global__ void __launch_bounds__(256) k_ctxred() {
    const int b = blockIdx.y;
    const int idx4 = blockIdx.x * 256 + threadIdx.x;    // float4 index, 0..16383
    const float4* src = (const float4*)g_pctx + (size_t)b * SK * 16384 + idx4;
    float4 s = make_float4(0.f, 0.f, 0.f, 0.f);
#pragma unroll
    for (int sk = 0; sk < SK; sk++) {
        const float4 p = __ldcs(src + (size_t)sk * 16384);
        s.x += p.x; s.y += p.y; s.z += p.z; s.w += p.w;
    }
    const size_t o = (size_t)b * M * D + idx4 * 4;
    split_store(g_cth, g_ctl, o + 0, s.x * 4.0f);
    split_store(g_cth, g_ctl, o + 1, s.y * 4.0f);
    split_store(g_cth, g_ctl, o + 2, s.z * 4.0f);
    split_store(g_cth, g_ctl, o + 3, s.w * 4.0f);
    if (blockIdx.x == 0) {                   // ksum: 256 threads = 256 m-cols
        float ks = 0.f;
#pragma unroll
        for (int sk = 0; sk < SK; sk++)
            ks += g_pksum[(size_t)(b * SK + sk) * M + threadIdx.x];
        g_ksum[b * M + threadIdx.x] = ks;
    }
}

extern "C" void kernel_launch(void* const* d_in, const int* in_sizes, int n_in,
                              void* d_out, int out_size) {
    const float* x     = (const float*)d_in[0];
    const float* gamma = (const float*)d_in[1];
    const float* beta  = (const float*)d_in[2];
    const float* proj  = (const float*)d_in[3];
    float* out = (float*)d_out;
    (void)in_sizes; (void)n_in; (void)out_size;

    cudaFuncSetAttribute(k_mma<0>, cudaFuncAttributeMaxDynamicSharedMemorySize, SMEM_MMA);
    cudaFuncSetAttribute(k_mma<1>, cudaFuncAttributeMaxDynamicSharedMemorySize, SMEM_MMA);
    cudaFuncSetAttribute(k_mma<2>, cudaFuncAttributeMaxDynamicSharedMemorySize, SMEM_MMA);

    k_pre<<<544, 256>>>(x, gamma, beta, proj);
    k_mma<0><<<dim3(S / 128, M / 128, B), 512, SMEM_MMA>>>(nullptr);
    k_mma<1><<<dim3(M / 128, D / 128, B * SK), 512, SMEM_MMA>>>(nullptr);
    k_ctxred<<<dim3(64, B), 256>>>();
    k_mma<2><<<dim3(S / 128, D / 128, B), 512, SMEM_MMA>>>(out);
}